// round 9
// baseline (speedup 1.0000x reference)
#include <cuda_runtime.h>
#include <math.h>

// Problem constants
#define BB 32
#define TT 4096
#define NN 11
#define FF 16
#define HH 32
#define TPB 32                 // t-values per block
#define THREADS 352            // TPB * NN
#define ROW 176                // NN*FF floats per (b,t)
#define XS_STRIDE 180          // padded shared stride (bank-conflict avoidance)

typedef unsigned long long u64;

// packed f32x2 FMA (sm_100+ PTX) — 2x fp32 FMA throughput vs FFMA-3reg
__device__ __forceinline__ u64 fma2(u64 a, u64 b, u64 c) {
    u64 d;
    asm("fma.rn.f32x2 %0, %1, %2, %3;" : "=l"(d) : "l"(a), "l"(b), "l"(c));
    return d;
}
__device__ __forceinline__ u64 pk2(float lo, float hi) {
    u64 r;
    asm("mov.b64 %0, {%1, %2};" : "=l"(r) : "f"(lo), "f"(hi));
    return r;
}
__device__ __forceinline__ float2 upk2(u64 v) {
    float2 f;
    asm("mov.b64 {%0, %1}, %2;" : "=f"(f.x), "=f"(f.y) : "l"(v));
    return f;
}

__global__ __launch_bounds__(THREADS)
void fused_proj_mlp_kernel(
    const float* __restrict__ x,          // [B,T,N,F]
    const int*   __restrict__ lab_idx,    // [B]
    const float* __restrict__ projection, // [LABS,N,N]
    const float* __restrict__ bias,       // [LABS,1,N,F]
    const float* __restrict__ w1,         // [F,H]
    const float* __restrict__ b1,         // [H]
    const float* __restrict__ ln_g,       // [H]
    const float* __restrict__ ln_b,       // [H]
    const float* __restrict__ w2,         // [H,F]
    const float* __restrict__ b2,         // [F]
    float* __restrict__ out)              // [B,T,N,F]
{
    __shared__ __align__(16) float xs[TPB * XS_STRIDE];   // padded x tile
    __shared__ __align__(16) float Ws[NN * NN];
    __shared__ __align__(16) float bias_s[NN * FF];
    __shared__ __align__(16) float w1s[FF * HH];
    __shared__ __align__(16) float w2s[HH * FF];
    __shared__ __align__(16) float b1s[HH];
    __shared__ __align__(16) float gs[HH];
    __shared__ __align__(16) float bls[HH];
    __shared__ __align__(16) float b2s[FF];

    const int tid = threadIdx.x;
    const int b   = blockIdx.y;
    const int t0  = blockIdx.x * TPB;
    const int lab = lab_idx[b];

    // ---- stage x tile: 32*176 = 5632 floats = 1408 float4 = 4 per thread ----
    {
        const float4* xg = (const float4*)(x + ((size_t)(b * TT + t0)) * ROW);
        #pragma unroll
        for (int i = 0; i < 4; i++) {
            int idx4 = tid + i * THREADS;          // 0..1407
            float4 v = xg[idx4];
            int e = idx4 * 4;
            int t = e / ROW;
            int r = e - t * ROW;
            *(float4*)(xs + t * XS_STRIDE + r) = v;
        }
    }
    // ---- stage params ----
    if (tid < NN * NN)   Ws[tid]     = projection[lab * NN * NN + tid];
    if (tid < NN * FF)   bias_s[tid] = bias[lab * NN * FF + tid];
    #pragma unroll
    for (int i = tid; i < FF * HH; i += THREADS) { w1s[i] = w1[i]; w2s[i] = w2[i]; }
    if (tid < HH) { b1s[tid] = b1[tid]; gs[tid] = ln_g[tid]; bls[tid] = ln_b[tid]; }
    if (tid < FF) b2s[tid] = b2[tid];
    __syncthreads();

    const int m  = tid % NN;   // output channel
    const int tl = tid / NN;   // local t
    const float* xrow = xs + tl * XS_STRIDE;

    // ---- projection: out[f] = sum_n x[t,n,f] * W[n,m] + bias[m,f] ----
    float wn[NN];
    #pragma unroll
    for (int n = 0; n < NN; n++) wn[n] = Ws[n * NN + m];

    u64 acc[8];
    #pragma unroll
    for (int k = 0; k < 8; k++) acc[k] = *(const u64*)(bias_s + m * FF + 2 * k);
    #pragma unroll
    for (int n = 0; n < NN; n++) {
        u64 w = pk2(wn[n], wn[n]);
        const u64* xr = (const u64*)(xrow + n * FF);
        #pragma unroll
        for (int k = 0; k < 8; k++) acc[k] = fma2(xr[k], w, acc[k]);
    }
    float ov[FF];
    #pragma unroll
    for (int k = 0; k < 8; k++) { float2 f = upk2(acc[k]); ov[2 * k] = f.x; ov[2 * k + 1] = f.y; }

    // ---- MLP1: h[j] = sum_f ov[f] * w1[f,j] + b1[j]  (packed over j) ----
    u64 h2[16];
    #pragma unroll
    for (int k = 0; k < 16; k++) h2[k] = *(const u64*)(b1s + 2 * k);
    #pragma unroll
    for (int f = 0; f < FF; f++) {
        u64 a = pk2(ov[f], ov[f]);
        const u64* wr = (const u64*)(w1s + f * HH);
        #pragma unroll
        for (int k = 0; k < 16; k++) h2[k] = fma2(a, wr[k], h2[k]);
    }

    // ---- LayerNorm + exact GELU ----
    float hv[HH];
    #pragma unroll
    for (int k = 0; k < 16; k++) { float2 f = upk2(h2[k]); hv[2 * k] = f.x; hv[2 * k + 1] = f.y; }
    float s = 0.f, sq = 0.f;
    #pragma unroll
    for (int j = 0; j < HH; j++) { s += hv[j]; sq += hv[j] * hv[j]; }
    const float mu   = s * (1.f / HH);
    const float var  = sq * (1.f / HH) - mu * mu;
    const float rstd = rsqrtf(var + 1e-5f);
    #pragma unroll
    for (int j = 0; j < HH; j++) {
        float v = (hv[j] - mu) * rstd * gs[j] + bls[j];
        hv[j] = 0.5f * v * (1.f + erff(v * 0.70710678118654752f));
    }

    // ---- MLP2: y[f] = sum_j hv[j] * w2[j,f] + b2[f]  (packed over f) ----
    u64 y2[8];
    #pragma unroll
    for (int k = 0; k < 8; k++) y2[k] = *(const u64*)(b2s + 2 * k);
    #pragma unroll
    for (int j = 0; j < HH; j++) {
        u64 a = pk2(hv[j], hv[j]);
        const u64* wr = (const u64*)(w2s + j * FF);
        #pragma unroll
        for (int k = 0; k < 8; k++) y2[k] = fma2(a, wr[k], y2[k]);
    }

    // ---- store, coalesced float4 ----
    float* yg = out + (((size_t)(b * TT + t0 + tl)) * NN + m) * FF;
    #pragma unroll
    for (int k = 0; k < 4; k++) {
        float2 a = upk2(y2[2 * k]);
        float2 c = upk2(y2[2 * k + 1]);
        *(float4*)(yg + 4 * k) = make_float4(a.x, a.y, c.x, c.y);
    }
}

extern "C" void kernel_launch(void* const* d_in, const int* in_sizes, int n_in,
                              void* d_out, int out_size) {
    const float* x          = (const float*)d_in[0];
    const int*   lab_idx    = (const int*)  d_in[1];
    const float* projection = (const float*)d_in[2];
    const float* bias       = (const float*)d_in[3];
    const float* w1         = (const float*)d_in[4];
    const float* b1         = (const float*)d_in[5];
    const float* ln_g       = (const float*)d_in[6];
    const float* ln_b       = (const float*)d_in[7];
    const float* w2         = (const float*)d_in[8];
    const float* b2         = (const float*)d_in[9];
    float* out = (float*)d_out;

    dim3 grid(TT / TPB, BB);   // (128, 32)
    fused_proj_mlp_kernel<<<grid, THREADS>>>(
        x, lab_idx, projection, bias, w1, b1, ln_g, ln_b, w2, b2, out);
}

// round 10
// speedup vs baseline: 1.0735x; 1.0735x over previous
#include <cuda_runtime.h>
#include <math.h>

// Problem constants
#define BB 32
#define TT 4096
#define NN 11
#define FF 16
#define HH 32
#define TPB 32                 // t-values per block
#define THREADS 176            // (TPB/2) * NN ; each thread does 2 t-rows
#define ROW 176                // NN*FF floats per (b,t)

typedef unsigned long long u64;

// packed f32x2 FMA (sm_100+)
__device__ __forceinline__ u64 fma2(u64 a, u64 b, u64 c) {
    u64 d;
    asm("fma.rn.f32x2 %0, %1, %2, %3;" : "=l"(d) : "l"(a), "l"(b), "l"(c));
    return d;
}
__device__ __forceinline__ u64 dup2(float v) {          // (v, v)
    u64 r;
    asm("mov.b64 %0, {%1, %1};" : "=l"(r) : "f"(v));
    return r;
}
__device__ __forceinline__ u64 pk2(float lo, float hi) {
    u64 r;
    asm("mov.b64 %0, {%1, %2};" : "=l"(r) : "f"(lo), "f"(hi));
    return r;
}
__device__ __forceinline__ float2 upk2(u64 v) {
    float2 f;
    asm("mov.b64 {%0, %1}, %2;" : "=f"(f.x), "=f"(f.y) : "l"(v));
    return f;
}

__global__ __launch_bounds__(THREADS, 2)
void fused_proj_mlp_kernel(
    const float* __restrict__ x,          // [B,T,N,F]
    const int*   __restrict__ lab_idx,    // [B]
    const float* __restrict__ projection, // [LABS,N,N]
    const float* __restrict__ bias,       // [LABS,1,N,F]
    const float* __restrict__ w1,         // [F,H]
    const float* __restrict__ b1,         // [H]
    const float* __restrict__ ln_g,       // [H]
    const float* __restrict__ ln_b,       // [H]
    const float* __restrict__ w2,         // [H,F]
    const float* __restrict__ b2,         // [F]
    float* __restrict__ out)              // [B,T,N,F]
{
    __shared__ __align__(16) float xs[TPB * ROW];     // flat copy of the x tile
    __shared__ __align__(16) float Ws[NN * NN];
    __shared__ __align__(16) float bias_s[NN * FF];
    __shared__ __align__(16) float w1s[FF * HH];
    __shared__ __align__(16) float w2s[HH * FF];
    __shared__ __align__(16) float b1s[HH];
    __shared__ __align__(16) float gs[HH];
    __shared__ __align__(16) float bls[HH];
    __shared__ __align__(16) float b2s[FF];

    const int tid = threadIdx.x;
    const int b   = blockIdx.y;
    const int t0  = blockIdx.x * TPB;
    const int lab = lab_idx[b];

    // ---- stage x tile: flat float4 copy (5632 floats = 1408 float4, 8/thread) ----
    {
        const float4* xg = (const float4*)(x + ((size_t)(b * TT + t0)) * ROW);
        float4* xd = (float4*)xs;
        #pragma unroll
        for (int i = 0; i < 8; i++) {
            int idx = tid + i * THREADS;
            xd[idx] = xg[idx];
        }
    }
    // ---- stage params ----
    if (tid < NN * NN)   Ws[tid]     = projection[lab * NN * NN + tid];
    if (tid < NN * FF)   bias_s[tid] = bias[lab * NN * FF + tid];
    #pragma unroll
    for (int i = tid; i < FF * HH; i += THREADS) { w1s[i] = w1[i]; w2s[i] = w2[i]; }
    if (tid < HH) { b1s[tid] = b1[tid]; gs[tid] = ln_g[tid]; bls[tid] = ln_b[tid]; }
    if (tid < FF) b2s[tid] = b2[tid];
    __syncthreads();

    const int m  = tid % NN;       // output channel (same for both rows)
    const int tl = tid / NN;       // 0..15 ; rows tl and tl+16

    // ---- projection: acc[f] = bias[m,f] + sum_n x[t,n,f] * W[n,m] ----
    u64 wnp[NN];
    #pragma unroll
    for (int n = 0; n < NN; n++) wnp[n] = dup2(Ws[n * NN + m]);

    u64 aA[8], aB[8];
    {
        const ulonglong2* bv = (const ulonglong2*)(bias_s + m * FF);
        #pragma unroll
        for (int q = 0; q < 4; q++) {
            ulonglong2 v = bv[q];
            aA[2*q] = v.x; aA[2*q+1] = v.y;
            aB[2*q] = v.x; aB[2*q+1] = v.y;
        }
    }
    {
        const ulonglong2* xA = (const ulonglong2*)(xs + tl * ROW);
        const ulonglong2* xB = (const ulonglong2*)(xs + (tl + 16) * ROW);
        #pragma unroll
        for (int n = 0; n < NN; n++) {
            u64 w = wnp[n];
            #pragma unroll
            for (int q = 0; q < 4; q++) {
                ulonglong2 va = xA[n * 4 + q];
                ulonglong2 vb = xB[n * 4 + q];
                aA[2*q]   = fma2(va.x, w, aA[2*q]);
                aA[2*q+1] = fma2(va.y, w, aA[2*q+1]);
                aB[2*q]   = fma2(vb.x, w, aB[2*q]);
                aB[2*q+1] = fma2(vb.y, w, aB[2*q+1]);
            }
        }
    }

    // ---- MLP1: h[j] = b1[j] + sum_f ov[f] * w1[f,j]  (weights loaded once, used for both rows) ----
    u64 hA[16], hB[16];
    {
        const ulonglong2* bv = (const ulonglong2*)b1s;
        #pragma unroll
        for (int q = 0; q < 8; q++) {
            ulonglong2 v = bv[q];
            hA[2*q] = v.x; hA[2*q+1] = v.y;
            hB[2*q] = v.x; hB[2*q+1] = v.y;
        }
    }
    #pragma unroll
    for (int p = 0; p < 8; p++) {                 // f = 2p, 2p+1
        float2 ua = upk2(aA[p]);
        float2 ub = upk2(aB[p]);
        #pragma unroll
        for (int s = 0; s < 2; s++) {
            int f = 2 * p + s;
            u64 ba = dup2(s == 0 ? ua.x : ua.y);
            u64 bb = dup2(s == 0 ? ub.x : ub.y);
            const ulonglong2* wr = (const ulonglong2*)(w1s + f * HH);
            #pragma unroll
            for (int q = 0; q < 8; q++) {
                ulonglong2 wv = wr[q];
                hA[2*q]   = fma2(ba, wv.x, hA[2*q]);
                hA[2*q+1] = fma2(ba, wv.y, hA[2*q+1]);
                hB[2*q]   = fma2(bb, wv.x, hB[2*q]);
                hB[2*q+1] = fma2(bb, wv.y, hB[2*q+1]);
            }
        }
    }

    // ---- LayerNorm + exact GELU, both rows ----
    float hvA[HH], hvB[HH];
    #pragma unroll
    for (int k = 0; k < 16; k++) {
        float2 fa = upk2(hA[k]); hvA[2*k] = fa.x; hvA[2*k+1] = fa.y;
        float2 fb = upk2(hB[k]); hvB[2*k] = fb.x; hvB[2*k+1] = fb.y;
    }
    {
        float sA = 0.f, qA = 0.f, sB = 0.f, qB = 0.f;
        #pragma unroll
        for (int j = 0; j < HH; j++) {
            sA += hvA[j]; qA += hvA[j] * hvA[j];
            sB += hvB[j]; qB += hvB[j] * hvB[j];
        }
        const float muA = sA * (1.f / HH), muB = sB * (1.f / HH);
        const float rA = rsqrtf(qA * (1.f / HH) - muA * muA + 1e-5f);
        const float rB = rsqrtf(qB * (1.f / HH) - muB * muB + 1e-5f);
        #pragma unroll
        for (int j = 0; j < HH; j++) {
            float vA = (hvA[j] - muA) * rA * gs[j] + bls[j];
            float vB = (hvB[j] - muB) * rB * gs[j] + bls[j];
            hvA[j] = 0.5f * vA * (1.f + erff(vA * 0.70710678118654752f));
            hvB[j] = 0.5f * vB * (1.f + erff(vB * 0.70710678118654752f));
        }
    }

    // ---- MLP2: y[f] = b2[f] + sum_j g[j] * w2[j,f] ----
    u64 yA[8], yB[8];
    {
        const ulonglong2* bv = (const ulonglong2*)b2s;
        #pragma unroll
        for (int q = 0; q < 4; q++) {
            ulonglong2 v = bv[q];
            yA[2*q] = v.x; yA[2*q+1] = v.y;
            yB[2*q] = v.x; yB[2*q+1] = v.y;
        }
    }
    #pragma unroll
    for (int j = 0; j < HH; j++) {
        u64 ga = dup2(hvA[j]);
        u64 gb = dup2(hvB[j]);
        const ulonglong2* wr = (const ulonglong2*)(w2s + j * FF);
        #pragma unroll
        for (int q = 0; q < 4; q++) {
            ulonglong2 wv = wr[q];
            yA[2*q]   = fma2(ga, wv.x, yA[2*q]);
            yA[2*q+1] = fma2(ga, wv.y, yA[2*q+1]);
            yB[2*q]   = fma2(gb, wv.x, yB[2*q]);
            yB[2*q+1] = fma2(gb, wv.y, yB[2*q+1]);
        }
    }

    // ---- store both rows, float4 ----
    float* ygA = out + (((size_t)(b * TT + t0 + tl)) * NN + m) * FF;
    float* ygB = out + (((size_t)(b * TT + t0 + tl + 16)) * NN + m) * FF;
    #pragma unroll
    for (int k = 0; k < 4; k++) {
        float2 a0 = upk2(yA[2*k]); float2 a1 = upk2(yA[2*k+1]);
        float2 b0 = upk2(yB[2*k]); float2 b1v = upk2(yB[2*k+1]);
        *(float4*)(ygA + 4*k) = make_float4(a0.x, a0.y, a1.x, a1.y);
        *(float4*)(ygB + 4*k) = make_float4(b0.x, b0.y, b1v.x, b1v.y);
    }
}

extern "C" void kernel_launch(void* const* d_in, const int* in_sizes, int n_in,
                              void* d_out, int out_size) {
    const float* x          = (const float*)d_in[0];
    const int*   lab_idx    = (const int*)  d_in[1];
    const float* projection = (const float*)d_in[2];
    const float* bias       = (const float*)d_in[3];
    const float* w1         = (const float*)d_in[4];
    const float* b1         = (const float*)d_in[5];
    const float* ln_g       = (const float*)d_in[6];
    const float* ln_b       = (const float*)d_in[7];
    const float* w2         = (const float*)d_in[8];
    const float* b2         = (const float*)d_in[9];
    float* out = (float*)d_out;

    dim3 grid(TT / TPB, BB);   // (128, 32)
    fused_proj_mlp_kernel<<<grid, THREADS>>>(
        x, lab_idx, projection, bias, w1, b1, ln_g, ln_b, w2, b2, out);
}